// round 2
// baseline (speedup 1.0000x reference)
#include <cuda_runtime.h>
#include <cuda_bf16.h>
#include <cstddef>
#include <math.h>

// Problem dims (fixed)
#define BB   8
#define NN   2048
#define DD   1024
#define H1   128
#define FF   28
#define DK   64
#define MM   (BB*NN)        // 16384
#define NSTEPS 4

// ---------------- scratch (static device arrays; no runtime allocation) -------------
__device__ float g_h[MM * H1];                    // gelu(hs@w1^T+b1)
__device__ float g_Q[MM * DK];
__device__ float g_K[MM * DK];
__device__ float g_V[MM * DK];
__device__ float g_charge[MM];
__device__ float g_chist[4 * MM];                 // charges after update 1..4
__device__ float g_recv[MM];                      // zero-invariant between launches
__device__ float g_out64[MM * DK];
__device__ float g_compat[(size_t)BB * NN * NN];  // 134 MB; lower triangle valid

// ---------------- generic fp32 GEMM  C[M,N] = epi(A[M,K] @ B[N,K]^T) -----------------
#define EPI_NONE 0
#define EPI_GELU_BIAS 1
#define EPI_ALPHA 2

template<int EPI>
__global__ void gemm_abt_kernel(const float* __restrict__ A, const float* __restrict__ B,
                                const float* __restrict__ bias, float* __restrict__ C,
                                int M, int N, int K, const float* __restrict__ alpha_ptr)
{
    __shared__ float As[16][64];
    __shared__ float Bs[16][64];
    const int bm = blockIdx.y * 64;
    const int bn = blockIdx.x * 64;
    const int tid = threadIdx.x;
    const int tx = tid & 15, ty = tid >> 4;
    const int lr = tid >> 2, lk = (tid & 3) << 2;

    float acc[4][4];
#pragma unroll
    for (int i = 0; i < 4; i++)
#pragma unroll
        for (int j = 0; j < 4; j++) acc[i][j] = 0.f;

    const float* Arow = A + (size_t)(bm + lr) * K;
    const float* Brow = B + (size_t)(bn + lr) * K;

    for (int k0 = 0; k0 < K; k0 += 16) {
        float4 a4 = *(const float4*)(Arow + k0 + lk);
        float4 b4 = *(const float4*)(Brow + k0 + lk);
        __syncthreads();
        As[lk+0][lr]=a4.x; As[lk+1][lr]=a4.y; As[lk+2][lr]=a4.z; As[lk+3][lr]=a4.w;
        Bs[lk+0][lr]=b4.x; Bs[lk+1][lr]=b4.y; Bs[lk+2][lr]=b4.z; Bs[lk+3][lr]=b4.w;
        __syncthreads();
#pragma unroll
        for (int k = 0; k < 16; k++) {
            float4 av = *(const float4*)(&As[k][ty << 2]);
            float4 bv = *(const float4*)(&Bs[k][tx << 2]);
            float ar[4] = {av.x, av.y, av.z, av.w};
            float br[4] = {bv.x, bv.y, bv.z, bv.w};
#pragma unroll
            for (int i = 0; i < 4; i++)
#pragma unroll
                for (int j = 0; j < 4; j++)
                    acc[i][j] = fmaf(ar[i], br[j], acc[i][j]);
        }
    }

    float alpha = 1.f;
    if (EPI == EPI_ALPHA) alpha = 0.2f / (1.f + expf(-(*alpha_ptr)));

#pragma unroll
    for (int i = 0; i < 4; i++) {
        int m = bm + (ty << 2) + i;
#pragma unroll
        for (int j = 0; j < 4; j++) {
            int n = bn + (tx << 2) + j;
            float v = acc[i][j];
            if (EPI == EPI_GELU_BIAS) {
                v += bias[n];
                v = 0.5f * v * (1.f + erff(v * 0.70710678118654752f));
            }
            if (EPI == EPI_ALPHA) v *= alpha;
            C[(size_t)m * N + n] = v;
        }
    }
}

// ---------------- features / Q / K / charge from h -----------------
__global__ void feat_qk_kernel(const float* __restrict__ w2, const float* __restrict__ b2,
                               const float* __restrict__ wq, const float* __restrict__ wk,
                               const float* __restrict__ wc, const float* __restrict__ bc)
{
    __shared__ float w2T[H1 * FF];   // [k][f]
    __shared__ float wqT[FF * DK];   // [f][d]
    __shared__ float wkT[FF * DK];
    __shared__ float wcs[FF];
    __shared__ float b2s[FF];
    __shared__ float hrow[8 * H1];
    __shared__ float feats[8 * FF];

    int tid = threadIdx.x;
    for (int idx = tid; idx < FF * H1; idx += 256) {
        int f = idx / H1, k = idx % H1;
        w2T[k * FF + f] = w2[idx];
    }
    for (int idx = tid; idx < DK * FF; idx += 256) {
        int d = idx / FF, f = idx % FF;
        wqT[f * DK + d] = wq[idx];
        wkT[f * DK + d] = wk[idx];
    }
    if (tid < FF) { wcs[tid] = wc[tid]; b2s[tid] = b2[tid]; }
    __syncthreads();

    int w = tid >> 5, lane = tid & 31;
    int g = blockIdx.x * 8 + w;
    const float* hr = g_h + (size_t)g * H1;
    hrow[w * H1 + lane      ] = hr[lane];
    hrow[w * H1 + lane + 32 ] = hr[lane + 32];
    hrow[w * H1 + lane + 64 ] = hr[lane + 64];
    hrow[w * H1 + lane + 96 ] = hr[lane + 96];
    __syncwarp();

    if (lane < FF) {
        float acc = b2s[lane];
#pragma unroll 4
        for (int k = 0; k < H1; k++)
            acc = fmaf(hrow[w * H1 + k], w2T[k * FF + lane], acc);
        feats[w * FF + lane] = 1.f / (1.f + expf(-acc));
    }
    __syncwarp();

    if (lane == 0) {
        float cc = bc[0];
        for (int f = 0; f < FF; f++) cc += feats[w * FF + f] * wcs[f];
        g_charge[g] = 1.f / (1.f + expf(-cc));
    }

#pragma unroll
    for (int dd = 0; dd < 2; dd++) {
        int d = lane + dd * 32;
        float q = 0.f, kk = 0.f;
#pragma unroll
        for (int f = 0; f < FF; f++) {
            float fv = feats[w * FF + f];
            q  = fmaf(fv, wqT[f * DK + d], q);
            kk = fmaf(fv, wkT[f * DK + d], kk);
        }
        g_Q[(size_t)g * DK + d] = q;
        g_K[(size_t)g * DK + d] = kk;
    }
}

// ---------------- compat = Q @ K^T / 8, lower-triangular tiles only -----------------
__global__ void qk_compat_kernel()
{
    int tj = blockIdx.x, ti = blockIdx.y, b = blockIdx.z;
    if (tj > ti) return;
    __shared__ float Qs[64][64];   // [k][m]
    __shared__ float Ks[64][64];   // [k][n]
    int tid = threadIdx.x;
    int lr = tid >> 2, lk = (tid & 3) << 2;
    const float* Qb = g_Q + ((size_t)b * NN + ti * 64 + lr) * DK;
    const float* Kb = g_K + ((size_t)b * NN + tj * 64 + lr) * DK;
#pragma unroll
    for (int kp = 0; kp < 64; kp += 16) {
        float4 a4 = *(const float4*)(Qb + kp + lk);
        float4 b4 = *(const float4*)(Kb + kp + lk);
        Qs[kp+lk+0][lr]=a4.x; Qs[kp+lk+1][lr]=a4.y; Qs[kp+lk+2][lr]=a4.z; Qs[kp+lk+3][lr]=a4.w;
        Ks[kp+lk+0][lr]=b4.x; Ks[kp+lk+1][lr]=b4.y; Ks[kp+lk+2][lr]=b4.z; Ks[kp+lk+3][lr]=b4.w;
    }
    __syncthreads();

    int tx = tid & 15, ty = tid >> 4;
    float acc[4][4];
#pragma unroll
    for (int i = 0; i < 4; i++)
#pragma unroll
        for (int j = 0; j < 4; j++) acc[i][j] = 0.f;
#pragma unroll
    for (int k = 0; k < 64; k++) {
        float4 av = *(const float4*)(&Qs[k][ty << 2]);
        float4 bv = *(const float4*)(&Ks[k][tx << 2]);
        float ar[4] = {av.x, av.y, av.z, av.w};
        float br[4] = {bv.x, bv.y, bv.z, bv.w};
#pragma unroll
        for (int i = 0; i < 4; i++)
#pragma unroll
            for (int j = 0; j < 4; j++)
                acc[i][j] = fmaf(ar[i], br[j], acc[i][j]);
    }
#pragma unroll
    for (int i = 0; i < 4; i++) {
        size_t row = (size_t)b * NN + ti * 64 + (ty << 2) + i;
#pragma unroll
        for (int j = 0; j < 4; j++)
            g_compat[row * NN + tj * 64 + (tx << 2) + j] = acc[i][j] * 0.125f;
    }
}

// ---------------- softmax pass t: row softmax of compat*m + column sums --------------
// block = 512 threads = 16 warps; warp w handles row r0+w of batch b.
__global__ void softmax_pass_kernel(int nterms, const float* __restrict__ step_ptr)
{
    extern __shared__ float sm[];
    float* rowbuf = sm;                    // 16*2048
    float* chs    = sm + 16 * NN;          // 4*2048
    float* invs   = chs + 4 * NN;          // 16

    int b = blockIdx.y, r0 = blockIdx.x * 16;
    int tid = threadIdx.x, w = tid >> 5, lane = tid & 31;
    float step = *step_ptr;

    for (int s = 0; s < nterms; s++)
        for (int j = tid; j < NN; j += 512)
            chs[s * NN + j] = g_chist[s * MM + b * NN + j];
    __syncthreads();

    int i = r0 + w;
    int len = i + 1;
    const float* crow = g_compat + ((size_t)b * NN + i) * NN;
    float* rb = rowbuf + w * NN;

    float a0 = 0.f, a1 = 0.f, a2 = 0.f, a3 = 0.f;
    if (nterms > 0) a0 = step * chs[i];
    if (nterms > 1) a1 = step * chs[NN + i];
    if (nterms > 2) a2 = step * chs[2 * NN + i];
    if (nterms > 3) a3 = step * chs[3 * NN + i];

    float mx = -3.4e38f;
    for (int j = lane; j < len; j += 32) {
        float m = 1.f;
        if (nterms > 0) m = fmaf(a0, chs[j], m);
        if (nterms > 1) m = fmaf(a1, chs[NN + j], m);
        if (nterms > 2) m = fmaf(a2, chs[2 * NN + j], m);
        if (nterms > 3) m = fmaf(a3, chs[3 * NN + j], m);
        float l = crow[j] * m;
        rb[j] = l;
        mx = fmaxf(mx, l);
    }
#pragma unroll
    for (int o = 16; o; o >>= 1) mx = fmaxf(mx, __shfl_xor_sync(0xffffffffu, mx, o));
    float s = 0.f;
    for (int j = lane; j < len; j += 32) {
        float e = expf(rb[j] - mx);
        rb[j] = e;
        s += e;
    }
#pragma unroll
    for (int o = 16; o; o >>= 1) s += __shfl_xor_sync(0xffffffffu, s, o);
    if (lane == 0) invs[w] = 1.f / s;
    __syncthreads();

    // column reduction: recv[j] += sum over warps whose row >= j
    int jmax = r0 + 16; if (jmax > NN) jmax = NN;
    for (int j = tid; j < jmax; j += 512) {
        float acc = 0.f;
        int wstart = (j > r0) ? (j - r0) : 0;
        for (int ww = wstart; ww < 16; ww++)
            acc += rowbuf[ww * NN + j] * invs[ww];
        atomicAdd(&g_recv[b * NN + j], acc);
    }
}

// ---------------- final softmax: overwrite compat with attn probabilities -----------
__global__ void softmax_final_kernel(const float* __restrict__ step_ptr)
{
    extern __shared__ float sm[];
    float* rowbuf = sm;
    float* chs    = sm + 16 * NN;

    int b = blockIdx.y, r0 = blockIdx.x * 16;
    int tid = threadIdx.x, w = tid >> 5, lane = tid & 31;
    float step = *step_ptr;

    for (int s = 0; s < 4; s++)
        for (int j = tid; j < NN; j += 512)
            chs[s * NN + j] = g_chist[s * MM + b * NN + j];
    __syncthreads();

    int i = r0 + w;
    int len = i + 1;
    float* crow = g_compat + ((size_t)b * NN + i) * NN;
    float* rb = rowbuf + w * NN;

    float a0 = step * chs[i];
    float a1 = step * chs[NN + i];
    float a2 = step * chs[2 * NN + i];
    float a3 = step * chs[3 * NN + i];

    float mx = -3.4e38f;
    for (int j = lane; j < len; j += 32) {
        float m = 1.f;
        m = fmaf(a0, chs[j], m);
        m = fmaf(a1, chs[NN + j], m);
        m = fmaf(a2, chs[2 * NN + j], m);
        m = fmaf(a3, chs[3 * NN + j], m);
        float l = crow[j] * m;
        rb[j] = l;
        mx = fmaxf(mx, l);
    }
#pragma unroll
    for (int o = 16; o; o >>= 1) mx = fmaxf(mx, __shfl_xor_sync(0xffffffffu, mx, o));
    float s = 0.f;
    for (int j = lane; j < len; j += 32) {
        float e = expf(rb[j] - mx);
        rb[j] = e;
        s += e;
    }
#pragma unroll
    for (int o = 16; o; o >>= 1) s += __shfl_xor_sync(0xffffffffu, s, o);
    float inv = 1.f / s;
    for (int j = lane; j < len; j += 32)
        crow[j] = rb[j] * inv;
}

// ---------------- charge update + recv re-zero -----------------
__global__ void charge_update_kernel(int t, const float* __restrict__ decay_ptr)
{
    int idx = blockIdx.x * 256 + threadIdx.x;
    float r = g_recv[idx];
    g_recv[idx] = 0.f;                       // restore zero-invariant
    float d = *decay_ptr;
    float sg = 1.f / (1.f + expf(-(r - 1.f)));
    float c = g_charge[idx] * (1.f - d * sg);
    g_charge[idx] = c;
    g_chist[t * MM + idx] = c;
}

// ---------------- out64 = attn @ V (causal; attn lives in g_compat) -----------------
__global__ void attn_v_kernel()
{
    int it = blockIdx.x, b = blockIdx.y;
    __shared__ float As2[16][64];   // [j][i]
    __shared__ float Vs[16][64];    // [j][d]
    int tid = threadIdx.x;
    int tx = tid & 15, ty = tid >> 4;
    int lr = tid >> 2, lk = (tid & 3) << 2;
    int vr = tid >> 4, vc = (tid & 15) << 2;
    int i0 = it * 64;
    const float* Ab = g_compat + (size_t)b * NN * NN;
    const float* Vb = g_V + (size_t)b * NN * DK;
    int ig = i0 + lr;

    float acc[4][4];
#pragma unroll
    for (int i = 0; i < 4; i++)
#pragma unroll
        for (int j = 0; j < 4; j++) acc[i][j] = 0.f;

    int kmax = i0 + 64;
    for (int k0 = 0; k0 < kmax; k0 += 16) {
        float4 a4 = *(const float4*)(Ab + (size_t)ig * NN + k0 + lk);
        if (k0 >= i0) {   // diagonal band: mask j > i
            if (k0 + lk + 0 > ig) a4.x = 0.f;
            if (k0 + lk + 1 > ig) a4.y = 0.f;
            if (k0 + lk + 2 > ig) a4.z = 0.f;
            if (k0 + lk + 3 > ig) a4.w = 0.f;
        }
        float4 v4 = *(const float4*)(Vb + (size_t)(k0 + vr) * DK + vc);
        __syncthreads();
        As2[lk+0][lr]=a4.x; As2[lk+1][lr]=a4.y; As2[lk+2][lr]=a4.z; As2[lk+3][lr]=a4.w;
        *(float4*)&Vs[vr][vc] = v4;
        __syncthreads();
#pragma unroll
        for (int k = 0; k < 16; k++) {
            float4 av = *(const float4*)(&As2[k][ty << 2]);
            float4 bv = *(const float4*)(&Vs[k][tx << 2]);
            float ar[4] = {av.x, av.y, av.z, av.w};
            float br[4] = {bv.x, bv.y, bv.z, bv.w};
#pragma unroll
            for (int i = 0; i < 4; i++)
#pragma unroll
                for (int j = 0; j < 4; j++)
                    acc[i][j] = fmaf(ar[i], br[j], acc[i][j]);
        }
    }
#pragma unroll
    for (int i = 0; i < 4; i++) {
        size_t row = (size_t)b * NN + i0 + (ty << 2) + i;
#pragma unroll
        for (int j = 0; j < 4; j++)
            g_out64[row * DK + (tx << 2) + j] = acc[i][j];
    }
}

// =====================================================================================
extern "C" void kernel_launch(void* const* d_in, const int* in_sizes, int n_in,
                              void* d_out, int out_size)
{
    const float* hs      = (const float*)d_in[0];
    // d_in[1] = attention_mask (all ones, unused by reference math)
    const float* w1      = (const float*)d_in[2];
    const float* b1      = (const float*)d_in[3];
    const float* w2      = (const float*)d_in[4];
    const float* b2      = (const float*)d_in[5];
    const float* wq      = (const float*)d_in[6];
    const float* wk      = (const float*)d_in[7];
    const float* wc      = (const float*)d_in[8];
    const float* bc      = (const float*)d_in[9];
    const float* step_p  = (const float*)d_in[10];
    const float* decay_p = (const float*)d_in[11];
    const float* wv      = (const float*)d_in[12];
    const float* wo      = (const float*)d_in[13];
    const float* alpha_p = (const float*)d_in[14];
    float* out = (float*)d_out;

    float *ph, *pV, *po64;
    cudaGetSymbolAddress((void**)&ph,   g_h);
    cudaGetSymbolAddress((void**)&pV,   g_V);
    cudaGetSymbolAddress((void**)&po64, g_out64);

    const int smem_pass = (16 * NN + 4 * NN + 16) * 4;   // ~164 KB
    cudaFuncSetAttribute(softmax_pass_kernel,
                         cudaFuncAttributeMaxDynamicSharedMemorySize, smem_pass);
    cudaFuncSetAttribute(softmax_final_kernel,
                         cudaFuncAttributeMaxDynamicSharedMemorySize, smem_pass);

    // 1) h = gelu(hs @ w1^T + b1)          [16384,128]
    gemm_abt_kernel<EPI_GELU_BIAS><<<dim3(H1 / 64, MM / 64), 256>>>(
        hs, w1, b1, ph, MM, H1, DD, nullptr);

    // 2) features -> Q, K, charge0
    feat_qk_kernel<<<MM / 8, 256>>>(w2, b2, wq, wk, wc, bc);

    // 3) V = hs @ wv^T                     [16384,64]
    gemm_abt_kernel<EPI_NONE><<<dim3(DK / 64, MM / 64), 256>>>(
        hs, wv, nullptr, pV, MM, DK, DD, nullptr);

    // 4) compat = Q @ K^T / 8 (lower-triangular tiles)
    qk_compat_kernel<<<dim3(NN / 64, NN / 64, BB), 256>>>();

    // 5) 4 charge iterations
    for (int t = 0; t < NSTEPS; t++) {
        softmax_pass_kernel<<<dim3(NN / 16, BB), 512, smem_pass>>>(t, step_p);
        charge_update_kernel<<<MM / 256, 256>>>(t, decay_p);
    }

    // 6) final softmax -> attn (overwrites g_compat)
    softmax_final_kernel<<<dim3(NN / 16, BB), 512, smem_pass>>>(step_p);

    // 7) out64 = attn @ V (causal)
    attn_v_kernel<<<dim3(NN / 64, BB), 256>>>();

    // 8) out = alpha * (out64 @ wo^T)
    gemm_abt_kernel<EPI_ALPHA><<<dim3(DD / 64, MM / 64), 256>>>(
        po64, wo, nullptr, out, MM, DD, DK, alpha_p);
}

// round 4
// speedup vs baseline: 1.2986x; 1.2986x over previous
#include <cuda_runtime.h>
#include <cuda_bf16.h>
#include <cstddef>
#include <math.h>

// Problem dims (fixed)
#define BB   8
#define NN   2048
#define DD   1024
#define H1   128
#define FF   28
#define DK   64
#define MM   (BB*NN)        // 16384
#define NSTEPS 4

// ---------------- scratch (static device arrays) -------------
__device__ float g_h[MM * H1];
__device__ float g_Q[MM * DK];
__device__ float g_K[MM * DK];
__device__ float g_V[MM * DK];
__device__ float g_VT[(size_t)BB * DK * NN];
__device__ float g_charge[MM];
__device__ float g_chist[4 * MM];
__device__ float g_recv[MM];                      // zero-invariant between launches
__device__ float g_out64[MM * DK];
__device__ float g_compat[(size_t)BB * NN * NN];  // 134 MB; lower triangle valid

#define EPI_NONE       0
#define EPI_GELU_BIAS  1
#define EPI_ALPHA      2
#define EPI_SCALE      3

// ================= high-throughput fp32 tile GEMM: C = epi(A[M,K] @ B[N,K]^T) ========
// 128x64 block tile, 256 threads, 8x4 per-thread microtile, double-buffered smem,
// one __syncthreads per 16-k chunk. Optional: TRI (skip tiles above diagonal),
// CAUSAL (zero A elements with col>row, cap K at bm+BM), SPLITK (atomicAdd epilogue).
#define TBM 128
#define TBN 64
#define TBK 16

template<int EPI, bool TRI, bool CAUSAL, bool SPLITK>
__global__ __launch_bounds__(256)
void gemm_tile_kernel(const float* __restrict__ A, const float* __restrict__ B,
                      const float* __restrict__ bias, float* __restrict__ C,
                      int N, int K,
                      size_t sA, size_t sB, size_t sC,
                      const float* __restrict__ alpha_ptr, int kslice)
{
    int bz = blockIdx.z;
    int bm, bn, ks;
    if (SPLITK) { ks = blockIdx.x; bn = 0; bm = blockIdx.y * TBM; }
    else        { ks = 0; bn = blockIdx.x * TBN; bm = blockIdx.y * TBM; }
    if (TRI && bn >= bm + TBM) return;     // tile entirely above diagonal

    const float* Ab = A + (size_t)bz * sA;
    const float* Bb = B + (size_t)bz * sB;
    float*       Cb = C + (size_t)bz * sC;

    int kmax = K;
    if (CAUSAL) kmax = min(K, bm + TBM);
    int c0 = 0, c1 = kmax / TBK;
    if (SPLITK) {
        int cps = kslice / TBK;
        c0 = ks * cps;
        c1 = min(c1, (ks + 1) * cps);
        if (c0 >= c1) return;
    }

    __shared__ float As[2][TBK][TBM + 4];
    __shared__ float Bs[2][TBK][TBN + 4];

    const int t  = threadIdx.x;
    const int tx = t & 15;          // n-direction (16 * 4 = 64)
    const int ty = t >> 4;          // m-direction (16 * 8 = 128)

    // global-load job mapping
    const int a_row  = t >> 2;                // 0..63 (second job: +64)
    const int a_kseg = (t & 3) << 2;          // 0,4,8,12
    const int b_row  = t >> 2;
    const int b_kseg = (t & 3) << 2;

    float acc[8][4];
#pragma unroll
    for (int i = 0; i < 8; i++)
#pragma unroll
        for (int j = 0; j < 4; j++) acc[i][j] = 0.f;

    float4 ra0, ra1, rb;

    // ---- prologue: load chunk c0, store to buffer 0 ----
    {
        int kbase = c0 * TBK;
        int col = kbase + a_kseg;
        int r0 = bm + a_row, r1 = bm + a_row + 64;
        ra0 = *(const float4*)(Ab + (size_t)r0 * K + col);
        ra1 = *(const float4*)(Ab + (size_t)r1 * K + col);
        if (CAUSAL) {
            if (col + 0 > r0) ra0.x = 0.f;
            if (col + 1 > r0) ra0.y = 0.f;
            if (col + 2 > r0) ra0.z = 0.f;
            if (col + 3 > r0) ra0.w = 0.f;
            if (col + 0 > r1) ra1.x = 0.f;
            if (col + 1 > r1) ra1.y = 0.f;
            if (col + 2 > r1) ra1.z = 0.f;
            if (col + 3 > r1) ra1.w = 0.f;
        }
        rb = *(const float4*)(Bb + (size_t)(bn + b_row) * K + kbase + b_kseg);
    }
    As[0][a_kseg+0][a_row] = ra0.x; As[0][a_kseg+1][a_row] = ra0.y;
    As[0][a_kseg+2][a_row] = ra0.z; As[0][a_kseg+3][a_row] = ra0.w;
    As[0][a_kseg+0][a_row+64] = ra1.x; As[0][a_kseg+1][a_row+64] = ra1.y;
    As[0][a_kseg+2][a_row+64] = ra1.z; As[0][a_kseg+3][a_row+64] = ra1.w;
    Bs[0][b_kseg+0][b_row] = rb.x; Bs[0][b_kseg+1][b_row] = rb.y;
    Bs[0][b_kseg+2][b_row] = rb.z; Bs[0][b_kseg+3][b_row] = rb.w;
    __syncthreads();

    int buf = 0;
    for (int c = c0; c < c1; c++) {
        if (c + 1 < c1) {
            int kbase = (c + 1) * TBK;
            int col = kbase + a_kseg;
            int r0 = bm + a_row, r1 = bm + a_row + 64;
            ra0 = *(const float4*)(Ab + (size_t)r0 * K + col);
            ra1 = *(const float4*)(Ab + (size_t)r1 * K + col);
            if (CAUSAL) {
                if (col + 0 > r0) ra0.x = 0.f;
                if (col + 1 > r0) ra0.y = 0.f;
                if (col + 2 > r0) ra0.z = 0.f;
                if (col + 3 > r0) ra0.w = 0.f;
                if (col + 0 > r1) ra1.x = 0.f;
                if (col + 1 > r1) ra1.y = 0.f;
                if (col + 2 > r1) ra1.z = 0.f;
                if (col + 3 > r1) ra1.w = 0.f;
            }
            rb = *(const float4*)(Bb + (size_t)(bn + b_row) * K + kbase + b_kseg);
        }
#pragma unroll
        for (int k = 0; k < TBK; k++) {
            float4 a0 = *(const float4*)&As[buf][k][ty * 8];
            float4 a1 = *(const float4*)&As[buf][k][ty * 8 + 4];
            float4 b0 = *(const float4*)&Bs[buf][k][tx * 4];
            float av[8] = {a0.x, a0.y, a0.z, a0.w, a1.x, a1.y, a1.z, a1.w};
            float bv[4] = {b0.x, b0.y, b0.z, b0.w};
#pragma unroll
            for (int i = 0; i < 8; i++)
#pragma unroll
                for (int j = 0; j < 4; j++)
                    acc[i][j] = fmaf(av[i], bv[j], acc[i][j]);
        }
        if (c + 1 < c1) {
            int nb = buf ^ 1;
            As[nb][a_kseg+0][a_row] = ra0.x; As[nb][a_kseg+1][a_row] = ra0.y;
            As[nb][a_kseg+2][a_row] = ra0.z; As[nb][a_kseg+3][a_row] = ra0.w;
            As[nb][a_kseg+0][a_row+64] = ra1.x; As[nb][a_kseg+1][a_row+64] = ra1.y;
            As[nb][a_kseg+2][a_row+64] = ra1.z; As[nb][a_kseg+3][a_row+64] = ra1.w;
            Bs[nb][b_kseg+0][b_row] = rb.x; Bs[nb][b_kseg+1][b_row] = rb.y;
            Bs[nb][b_kseg+2][b_row] = rb.z; Bs[nb][b_kseg+3][b_row] = rb.w;
            __syncthreads();
            buf = nb;
        }
    }

    // ---- epilogue ----
    float alpha = 1.f;
    if (EPI == EPI_ALPHA) alpha = 0.2f / (1.f + expf(-(*alpha_ptr)));

#pragma unroll
    for (int i = 0; i < 8; i++) {
        int row = bm + ty * 8 + i;
        int col = bn + tx * 4;
        if (SPLITK) {
#pragma unroll
            for (int j = 0; j < 4; j++)
                atomicAdd(&Cb[(size_t)row * N + col + j], acc[i][j]);
        } else {
            float4 v;
            float vv[4];
#pragma unroll
            for (int j = 0; j < 4; j++) {
                float x = acc[i][j];
                if (EPI == EPI_GELU_BIAS) {
                    x += bias[col + j];
                    x = 0.5f * x * (1.f + erff(x * 0.70710678118654752f));
                }
                if (EPI == EPI_ALPHA) x *= alpha;
                if (EPI == EPI_SCALE) x *= 0.125f;
                vv[j] = x;
            }
            v.x = vv[0]; v.y = vv[1]; v.z = vv[2]; v.w = vv[3];
            *(float4*)&Cb[(size_t)row * N + col] = v;
        }
    }
}

// ---------------- V transpose: g_VT[b][d][j] = g_V[b][j][d] -----------------
__global__ void transpose_v_kernel()
{
    __shared__ float tile[32][33];
    int b = blockIdx.z;
    int j0 = blockIdx.x * 32;
    int d0 = blockIdx.y * 32;
    int x = threadIdx.x, y = threadIdx.y;   // 32 x 8
    const float* Vb = g_V + (size_t)b * NN * DK;
    float* VTb = g_VT + (size_t)b * DK * NN;
#pragma unroll
    for (int yy = y; yy < 32; yy += 8)
        tile[yy][x] = Vb[(size_t)(j0 + yy) * DK + d0 + x];
    __syncthreads();
#pragma unroll
    for (int yy = y; yy < 32; yy += 8)
        VTb[(size_t)(d0 + yy) * NN + j0 + x] = tile[x][yy];
}

__global__ void zero_out64_kernel()
{
    int idx = blockIdx.x * 1024 + threadIdx.x;
    g_out64[idx] = 0.f;
}

// ---------------- features / Q / K / charge from h -----------------
__global__ void feat_qk_kernel(const float* __restrict__ w2, const float* __restrict__ b2,
                               const float* __restrict__ wq, const float* __restrict__ wk,
                               const float* __restrict__ wc, const float* __restrict__ bc)
{
    __shared__ float w2T[H1 * FF];
    __shared__ float wqT[FF * DK];
    __shared__ float wkT[FF * DK];
    __shared__ float wcs[FF];
    __shared__ float b2s[FF];
    __shared__ float hrow[8 * H1];
    __shared__ float feats[8 * FF];

    int tid = threadIdx.x;
    for (int idx = tid; idx < FF * H1; idx += 256) {
        int f = idx / H1, k = idx % H1;
        w2T[k * FF + f] = w2[idx];
    }
    for (int idx = tid; idx < DK * FF; idx += 256) {
        int d = idx / FF, f = idx % FF;
        wqT[f * DK + d] = wq[idx];
        wkT[f * DK + d] = wk[idx];
    }
    if (tid < FF) { wcs[tid] = wc[tid]; b2s[tid] = b2[tid]; }
    __syncthreads();

    int w = tid >> 5, lane = tid & 31;
    int g = blockIdx.x * 8 + w;
    const float* hr = g_h + (size_t)g * H1;
    hrow[w * H1 + lane      ] = hr[lane];
    hrow[w * H1 + lane + 32 ] = hr[lane + 32];
    hrow[w * H1 + lane + 64 ] = hr[lane + 64];
    hrow[w * H1 + lane + 96 ] = hr[lane + 96];
    __syncwarp();

    if (lane < FF) {
        float acc = b2s[lane];
#pragma unroll 4
        for (int k = 0; k < H1; k++)
            acc = fmaf(hrow[w * H1 + k], w2T[k * FF + lane], acc);
        feats[w * FF + lane] = 1.f / (1.f + expf(-acc));
    }
    __syncwarp();

    if (lane == 0) {
        float cc = bc[0];
        for (int f = 0; f < FF; f++) cc += feats[w * FF + f] * wcs[f];
        g_charge[g] = 1.f / (1.f + expf(-cc));
    }

#pragma unroll
    for (int dd = 0; dd < 2; dd++) {
        int d = lane + dd * 32;
        float q = 0.f, kk = 0.f;
#pragma unroll
        for (int f = 0; f < FF; f++) {
            float fv = feats[w * FF + f];
            q  = fmaf(fv, wqT[f * DK + d], q);
            kk = fmaf(fv, wkT[f * DK + d], kk);
        }
        g_Q[(size_t)g * DK + d] = q;
        g_K[(size_t)g * DK + d] = kk;
    }
}

// ---------------- softmax pass t: row softmax of compat*m + column sums --------------
__global__ void softmax_pass_kernel(int nterms, const float* __restrict__ step_ptr)
{
    extern __shared__ float sm[];
    float* rowbuf = sm;                    // 16*2048
    float* chs    = sm + 16 * NN;          // 4*2048
    float* invs   = chs + 4 * NN;          // 16

    int b = blockIdx.y, r0 = blockIdx.x * 16;
    int tid = threadIdx.x, w = tid >> 5, lane = tid & 31;
    float step = *step_ptr;

    for (int s = 0; s < nterms; s++)
        for (int j = tid; j < NN; j += 512)
            chs[s * NN + j] = g_chist[s * MM + b * NN + j];
    __syncthreads();

    int i = r0 + w;
    int len = i + 1;
    const float* crow = g_compat + ((size_t)b * NN + i) * NN;
    float* rb = rowbuf + w * NN;

    float a0 = 0.f, a1 = 0.f, a2 = 0.f, a3 = 0.f;
    if (nterms > 0) a0 = step * chs[i];
    if (nterms > 1) a1 = step * chs[NN + i];
    if (nterms > 2) a2 = step * chs[2 * NN + i];
    if (nterms > 3) a3 = step * chs[3 * NN + i];

    float mx = -3.4e38f;
    for (int j = lane; j < len; j += 32) {
        float m = 1.f;
        if (nterms > 0) m = fmaf(a0, chs[j], m);
        if (nterms > 1) m = fmaf(a1, chs[NN + j], m);
        if (nterms > 2) m = fmaf(a2, chs[2 * NN + j], m);
        if (nterms > 3) m = fmaf(a3, chs[3 * NN + j], m);
        float l = crow[j] * m;
        rb[j] = l;
        mx = fmaxf(mx, l);
    }
#pragma unroll
    for (int o = 16; o; o >>= 1) mx = fmaxf(mx, __shfl_xor_sync(0xffffffffu, mx, o));
    float s = 0.f;
    for (int j = lane; j < len; j += 32) {
        float e = expf(rb[j] - mx);
        rb[j] = e;
        s += e;
    }
#pragma unroll
    for (int o = 16; o; o >>= 1) s += __shfl_xor_sync(0xffffffffu, s, o);
    if (lane == 0) invs[w] = 1.f / s;
    __syncthreads();

    int jmax = r0 + 16; if (jmax > NN) jmax = NN;
    for (int j = tid; j < jmax; j += 512) {
        float acc = 0.f;
        int wstart = (j > r0) ? (j - r0) : 0;
        for (int ww = wstart; ww < 16; ww++)
            acc += rowbuf[ww * NN + j] * invs[ww];
        atomicAdd(&g_recv[b * NN + j], acc);
    }
}

// ---------------- final softmax: overwrite compat with attn probabilities -----------
__global__ void softmax_final_kernel(const float* __restrict__ step_ptr)
{
    extern __shared__ float sm[];
    float* rowbuf = sm;
    float* chs    = sm + 16 * NN;

    int b = blockIdx.y, r0 = blockIdx.x * 16;
    int tid = threadIdx.x, w = tid >> 5, lane = tid & 31;
    float step = *step_ptr;

    for (int s = 0; s < 4; s++)
        for (int j = tid; j < NN; j += 512)
            chs[s * NN + j] = g_chist[s * MM + b * NN + j];
    __syncthreads();

    int i = r0 + w;
    int len = i + 1;
    float* crow = g_compat + ((size_t)b * NN + i) * NN;
    float* rb = rowbuf + w * NN;

    float a0 = step * chs[i];
    float a1 = step * chs[NN + i];
    float a2 = step * chs[2 * NN + i];
    float a3 = step * chs[3 * NN + i];

    float mx = -3.4e38f;
    for (int j = lane; j < len; j += 32) {
        float m = 1.f;
        m = fmaf(a0, chs[j], m);
        m = fmaf(a1, chs[NN + j], m);
        m = fmaf(a2, chs[2 * NN + j], m);
        m = fmaf(a3, chs[3 * NN + j], m);
        float l = crow[j] * m;
        rb[j] = l;
        mx = fmaxf(mx, l);
    }
#pragma unroll
    for (int o = 16; o; o >>= 1) mx = fmaxf(mx, __shfl_xor_sync(0xffffffffu, mx, o));
    float s = 0.f;
    for (int j = lane; j < len; j += 32) {
        float e = expf(rb[j] - mx);
        rb[j] = e;
        s += e;
    }
#pragma unroll
    for (int o = 16; o; o >>= 1) s += __shfl_xor_sync(0xffffffffu, s, o);
    float inv = 1.f / s;
    for (int j = lane; j < len; j += 32)
        crow[j] = rb[j] * inv;
}

// ---------------- charge update + recv re-zero -----------------
__global__ void charge_update_kernel(int t, const float* __restrict__ decay_ptr)
{
    int idx = blockIdx.x * 256 + threadIdx.x;
    float r = g_recv[idx];
    g_recv[idx] = 0.f;
    float d = *decay_ptr;
    float sg = 1.f / (1.f + expf(-(r - 1.f)));
    float c = g_charge[idx] * (1.f - d * sg);
    g_charge[idx] = c;
    g_chist[t * MM + idx] = c;
}

// =====================================================================================
extern "C" void kernel_launch(void* const* d_in, const int* in_sizes, int n_in,
                              void* d_out, int out_size)
{
    const float* hs      = (const float*)d_in[0];
    const float* w1      = (const float*)d_in[2];
    const float* b1      = (const float*)d_in[3];
    const float* w2      = (const float*)d_in[4];
    const float* b2      = (const float*)d_in[5];
    const float* wq      = (const float*)d_in[6];
    const float* wk      = (const float*)d_in[7];
    const float* wc      = (const float*)d_in[8];
    const float* bc      = (const float*)d_in[9];
    const float* step_p  = (const float*)d_in[10];
    const float* decay_p = (const float*)d_in[11];
    const float* wv      = (const float*)d_in[12];
    const float* wo      = (const float*)d_in[13];
    const float* alpha_p = (const float*)d_in[14];
    float* out = (float*)d_out;

    float *ph, *pV, *pVT, *pQ, *pK, *po64, *pC;
    cudaGetSymbolAddress((void**)&ph,   g_h);
    cudaGetSymbolAddress((void**)&pV,   g_V);
    cudaGetSymbolAddress((void**)&pVT,  g_VT);
    cudaGetSymbolAddress((void**)&pQ,   g_Q);
    cudaGetSymbolAddress((void**)&pK,   g_K);
    cudaGetSymbolAddress((void**)&po64, g_out64);
    cudaGetSymbolAddress((void**)&pC,   g_compat);

    const int smem_pass = (16 * NN + 4 * NN + 16) * 4;   // ~164 KB
    cudaFuncSetAttribute(softmax_pass_kernel,
                         cudaFuncAttributeMaxDynamicSharedMemorySize, smem_pass);
    cudaFuncSetAttribute(softmax_final_kernel,
                         cudaFuncAttributeMaxDynamicSharedMemorySize, smem_pass);

    // 1) h = gelu(hs @ w1^T + b1)          [16384,128]
    gemm_tile_kernel<EPI_GELU_BIAS,false,false,false><<<dim3(H1/TBN, MM/TBM, 1), 256>>>(
        hs, w1, b1, ph, H1, DD, 0, 0, 0, nullptr, 0);

    // 2) features -> Q, K, charge0
    feat_qk_kernel<<<MM / 8, 256>>>(w2, b2, wq, wk, wc, bc);

    // 3) V = hs @ wv^T                     [16384,64]
    gemm_tile_kernel<EPI_NONE,false,false,false><<<dim3(DK/TBN, MM/TBM, 1), 256>>>(
        hs, wv, nullptr, pV, DK, DD, 0, 0, 0, nullptr, 0);

    // 4) VT[b][d][j] = V[b][j][d]
    transpose_v_kernel<<<dim3(NN/32, DK/32, BB), dim3(32, 8)>>>();

    // 5) compat = Q @ K^T / 8 (triangular tile set)
    gemm_tile_kernel<EPI_SCALE,true,false,false><<<dim3(NN/TBN, NN/TBM, BB), 256>>>(
        pQ, pK, nullptr, pC, NN, DK,
        (size_t)NN*DK, (size_t)NN*DK, (size_t)NN*NN, nullptr, 0);

    // 6) 4 charge iterations
    for (int t = 0; t < NSTEPS; t++) {
        softmax_pass_kernel<<<dim3(NN/16, BB), 512, smem_pass>>>(t, step_p);
        charge_update_kernel<<<MM/256, 256>>>(t, decay_p);
    }

    // 7) final softmax -> attn (overwrites g_compat)
    softmax_final_kernel<<<dim3(NN/16, BB), 512, smem_pass>>>(step_p);

    // 8) out64 = attn @ V (causal, split-K=4, atomic accumulate)
    zero_out64_kernel<<<(MM*DK)/1024, 1024>>>();
    gemm_tile_kernel<EPI_NONE,false,true,true><<<dim3(4, NN/TBM, BB), 256>>>(
        pC, pVT, nullptr, po64, DK, NN,
        (size_t)NN*NN, (size_t)DK*NN, (size_t)NN*DK, nullptr, 512);

    // 9) out = alpha * (out64 @ wo^T)
    gemm_tile_kernel<EPI_ALPHA,false,false,false><<<dim3(DD/TBN, MM/TBM, 1), 256>>>(
        po64, wo, nullptr, out, DD, DK, 0, 0, 0, alpha_p, 0);
}

// round 6
// speedup vs baseline: 1.3078x; 1.0071x over previous
#include <cuda_runtime.h>
#include <cuda_bf16.h>
#include <cstddef>
#include <math.h>

// Problem dims (fixed)
#define BB   8
#define NN   2048
#define DD   1024
#define H1   128
#define FF   28
#define DK   64
#define MM   (BB*NN)        // 16384
#define NSTEPS 4

// ---------------- scratch (static device arrays) -------------
__device__ float g_h[MM * H1];
__device__ float g_Q[MM * DK];
__device__ float g_K[MM * DK];
__device__ float g_V[MM * DK];
__device__ float g_VT[(size_t)BB * DK * NN];
__device__ float g_charge[MM];
__device__ float g_chist[4 * MM];
__device__ float g_recv[MM];                      // zero-invariant between launches
__device__ float g_rowinv[MM];
__device__ float g_out64[MM * DK];
__device__ float g_compat[(size_t)BB * NN * NN];  // 134 MB; lower triangle valid

#define EPI_NONE       0
#define EPI_GELU_BIAS  1
#define EPI_ALPHA      2
#define EPI_SCALE      3

// ================= high-throughput fp32 tile GEMM: C = epi(A[M,K] @ B[N,K]^T) ========
#define TBM 128
#define TBN 64
#define TBK 16

template<int EPI, bool TRI>
__global__ __launch_bounds__(256)
void gemm_tile_kernel(const float* __restrict__ A, const float* __restrict__ B,
                      const float* __restrict__ bias, float* __restrict__ C,
                      int N, int K,
                      size_t sA, size_t sB, size_t sC,
                      const float* __restrict__ alpha_ptr)
{
    int bz = blockIdx.z;
    int bn = blockIdx.x * TBN;
    int bm = blockIdx.y * TBM;
    if (TRI && bn >= bm + TBM) return;     // tile entirely above diagonal

    const float* Ab = A + (size_t)bz * sA;
    const float* Bb = B + (size_t)bz * sB;
    float*       Cb = C + (size_t)bz * sC;

    int c1 = K / TBK;

    __shared__ float As[2][TBK][TBM + 4];
    __shared__ float Bs[2][TBK][TBN + 4];

    const int t  = threadIdx.x;
    const int tx = t & 15;
    const int ty = t >> 4;
    const int a_row  = t >> 2;
    const int a_kseg = (t & 3) << 2;
    const int b_row  = t >> 2;
    const int b_kseg = (t & 3) << 2;

    float acc[8][4];
#pragma unroll
    for (int i = 0; i < 8; i++)
#pragma unroll
        for (int j = 0; j < 4; j++) acc[i][j] = 0.f;

    float4 ra0, ra1, rb;

    {
        int col = a_kseg;
        ra0 = *(const float4*)(Ab + (size_t)(bm + a_row) * K + col);
        ra1 = *(const float4*)(Ab + (size_t)(bm + a_row + 64) * K + col);
        rb  = *(const float4*)(Bb + (size_t)(bn + b_row) * K + b_kseg);
    }
    As[0][a_kseg+0][a_row] = ra0.x; As[0][a_kseg+1][a_row] = ra0.y;
    As[0][a_kseg+2][a_row] = ra0.z; As[0][a_kseg+3][a_row] = ra0.w;
    As[0][a_kseg+0][a_row+64] = ra1.x; As[0][a_kseg+1][a_row+64] = ra1.y;
    As[0][a_kseg+2][a_row+64] = ra1.z; As[0][a_kseg+3][a_row+64] = ra1.w;
    Bs[0][b_kseg+0][b_row] = rb.x; Bs[0][b_kseg+1][b_row] = rb.y;
    Bs[0][b_kseg+2][b_row] = rb.z; Bs[0][b_kseg+3][b_row] = rb.w;
    __syncthreads();

    int buf = 0;
    for (int c = 0; c < c1; c++) {
        if (c + 1 < c1) {
            int col = (c + 1) * TBK + a_kseg;
            ra0 = *(const float4*)(Ab + (size_t)(bm + a_row) * K + col);
            ra1 = *(const float4*)(Ab + (size_t)(bm + a_row + 64) * K + col);
            rb  = *(const float4*)(Bb + (size_t)(bn + b_row) * K + (c + 1) * TBK + b_kseg);
        }
#pragma unroll
        for (int k = 0; k < TBK; k++) {
            float4 a0 = *(const float4*)&As[buf][k][ty * 8];
            float4 a1 = *(const float4*)&As[buf][k][ty * 8 + 4];
            float4 b0 = *(const float4*)&Bs[buf][k][tx * 4];
            float av[8] = {a0.x, a0.y, a0.z, a0.w, a1.x, a1.y, a1.z, a1.w};
            float bv[4] = {b0.x, b0.y, b0.z, b0.w};
#pragma unroll
            for (int i = 0; i < 8; i++)
#pragma unroll
                for (int j = 0; j < 4; j++)
                    acc[i][j] = fmaf(av[i], bv[j], acc[i][j]);
        }
        if (c + 1 < c1) {
            int nb = buf ^ 1;
            As[nb][a_kseg+0][a_row] = ra0.x; As[nb][a_kseg+1][a_row] = ra0.y;
            As[nb][a_kseg+2][a_row] = ra0.z; As[nb][a_kseg+3][a_row] = ra0.w;
            As[nb][a_kseg+0][a_row+64] = ra1.x; As[nb][a_kseg+1][a_row+64] = ra1.y;
            As[nb][a_kseg+2][a_row+64] = ra1.z; As[nb][a_kseg+3][a_row+64] = ra1.w;
            Bs[nb][b_kseg+0][b_row] = rb.x; Bs[nb][b_kseg+1][b_row] = rb.y;
            Bs[nb][b_kseg+2][b_row] = rb.z; Bs[nb][b_kseg+3][b_row] = rb.w;
            __syncthreads();
            buf = nb;
        }
    }

    float alpha = 1.f;
    if (EPI == EPI_ALPHA) alpha = 0.2f / (1.f + expf(-(*alpha_ptr)));

#pragma unroll
    for (int i = 0; i < 8; i++) {
        int row = bm + ty * 8 + i;
        int col = bn + tx * 4;
        float4 v;
        float vv[4];
#pragma unroll
        for (int j = 0; j < 4; j++) {
            float x = acc[i][j];
            if (EPI == EPI_GELU_BIAS) {
                x += bias[col + j];
                x = 0.5f * x * (1.f + erff(x * 0.70710678118654752f));
            }
            if (EPI == EPI_ALPHA) x *= alpha;
            if (EPI == EPI_SCALE) x *= 0.125f;
            vv[j] = x;
        }
        v.x = vv[0]; v.y = vv[1]; v.z = vv[2]; v.w = vv[3];
        *(float4*)&Cb[(size_t)row * N + col] = v;
    }
}

// ============== fused attn@V: out64 += (exp(compat*m)*rowinv) @ VT, split-K ==========
__global__ __launch_bounds__(256)
void attn_v_fused_kernel(const float* __restrict__ step_ptr)
{
    const int b = blockIdx.z;
    const int ks = blockIdx.x;             // k-slice 0..3 (512 cols each)
    const int bm = blockIdx.y * TBM;

    const int cps = 512 / TBK;             // 32 chunks per slice
    int kmax = min(NN, bm + TBM);
    int c0 = ks * cps;
    int c1 = min(kmax / TBK, (ks + 1) * cps);
    if (c0 >= c1) return;

    __shared__ float As[2][TBK][TBM + 4];
    __shared__ float Bs[2][TBK][TBN + 4];
    __shared__ float chs_s[4][512];
    __shared__ float acoef[4][TBM];
    __shared__ float rinv_s[TBM];

    const float step = *step_ptr;
    const float* Cb  = g_compat + (size_t)b * NN * NN;
    const float* VTb = g_VT + (size_t)b * DK * NN;

    const int t = threadIdx.x;
    const int jbase = ks * 512;
    for (int idx = t; idx < 4 * 512; idx += 256) {
        int s = idx >> 9, j = idx & 511;
        chs_s[s][j] = g_chist[s * MM + b * NN + jbase + j];
    }
    for (int idx = t; idx < TBM; idx += 256) {
        int r = b * NN + bm + idx;
        rinv_s[idx] = g_rowinv[r];
        acoef[0][idx] = step * g_chist[0 * MM + r];
        acoef[1][idx] = step * g_chist[1 * MM + r];
        acoef[2][idx] = step * g_chist[2 * MM + r];
        acoef[3][idx] = step * g_chist[3 * MM + r];
    }
    __syncthreads();

    const int tx = t & 15;
    const int ty = t >> 4;
    const int a_row  = t >> 2;
    const int a_kseg = (t & 3) << 2;
    const int b_row  = t >> 2;
    const int b_kseg = (t & 3) << 2;

    // per-thread row constants
    const int r0l = a_row, r1l = a_row + 64;
    const float c00 = acoef[0][r0l], c01 = acoef[1][r0l], c02 = acoef[2][r0l], c03 = acoef[3][r0l];
    const float c10 = acoef[0][r1l], c11 = acoef[1][r1l], c12 = acoef[2][r1l], c13 = acoef[3][r1l];
    const float ri0 = rinv_s[r0l], ri1 = rinv_s[r1l];
    const int gr0 = bm + r0l, gr1 = bm + r1l;

    float acc[8][4];
#pragma unroll
    for (int i = 0; i < 8; i++)
#pragma unroll
        for (int j = 0; j < 4; j++) acc[i][j] = 0.f;

    float4 ra0, ra1, rb;

    auto loadA = [&](int c, float4& o0, float4& o1) {
        int col = c * TBK + a_kseg;          // global j of first component
        float4 a0 = *(const float4*)(Cb + (size_t)gr0 * NN + col);
        float4 a1 = *(const float4*)(Cb + (size_t)gr1 * NN + col);
        int jl = col - jbase;
        float aa0[4] = {a0.x, a0.y, a0.z, a0.w};
        float aa1[4] = {a1.x, a1.y, a1.z, a1.w};
        float oo0[4], oo1[4];
#pragma unroll
        for (int q = 0; q < 4; q++) {
            float h0 = chs_s[0][jl + q], h1 = chs_s[1][jl + q];
            float h2 = chs_s[2][jl + q], h3 = chs_s[3][jl + q];
            float m0 = 1.f + c00 * h0 + c01 * h1 + c02 * h2 + c03 * h3;
            float m1 = 1.f + c10 * h0 + c11 * h1 + c12 * h2 + c13 * h3;
            oo0[q] = (col + q <= gr0) ? __expf(aa0[q] * m0) * ri0 : 0.f;
            oo1[q] = (col + q <= gr1) ? __expf(aa1[q] * m1) * ri1 : 0.f;
        }
        o0.x = oo0[0]; o0.y = oo0[1]; o0.z = oo0[2]; o0.w = oo0[3];
        o1.x = oo1[0]; o1.y = oo1[1]; o1.z = oo1[2]; o1.w = oo1[3];
    };

    loadA(c0, ra0, ra1);
    rb = *(const float4*)(VTb + (size_t)b_row * NN + c0 * TBK + b_kseg);

    As[0][a_kseg+0][a_row] = ra0.x; As[0][a_kseg+1][a_row] = ra0.y;
    As[0][a_kseg+2][a_row] = ra0.z; As[0][a_kseg+3][a_row] = ra0.w;
    As[0][a_kseg+0][a_row+64] = ra1.x; As[0][a_kseg+1][a_row+64] = ra1.y;
    As[0][a_kseg+2][a_row+64] = ra1.z; As[0][a_kseg+3][a_row+64] = ra1.w;
    Bs[0][b_kseg+0][b_row] = rb.x; Bs[0][b_kseg+1][b_row] = rb.y;
    Bs[0][b_kseg+2][b_row] = rb.z; Bs[0][b_kseg+3][b_row] = rb.w;
    __syncthreads();

    int buf = 0;
    for (int c = c0; c < c1; c++) {
        if (c + 1 < c1) {
            loadA(c + 1, ra0, ra1);
            rb = *(const float4*)(VTb + (size_t)b_row * NN + (c + 1) * TBK + b_kseg);
        }
#pragma unroll
        for (int k = 0; k < TBK; k++) {
            float4 a0 = *(const float4*)&As[buf][k][ty * 8];
            float4 a1 = *(const float4*)&As[buf][k][ty * 8 + 4];
            float4 b0 = *(const float4*)&Bs[buf][k][tx * 4];
            float av[8] = {a0.x, a0.y, a0.z, a0.w, a1.x, a1.y, a1.z, a1.w};
            float bv[4] = {b0.x, b0.y, b0.z, b0.w};
#pragma unroll
            for (int i = 0; i < 8; i++)
#pragma unroll
                for (int j = 0; j < 4; j++)
                    acc[i][j] = fmaf(av[i], bv[j], acc[i][j]);
        }
        if (c + 1 < c1) {
            int nb = buf ^ 1;
            As[nb][a_kseg+0][a_row] = ra0.x; As[nb][a_kseg+1][a_row] = ra0.y;
            As[nb][a_kseg+2][a_row] = ra0.z; As[nb][a_kseg+3][a_row] = ra0.w;
            As[nb][a_kseg+0][a_row+64] = ra1.x; As[nb][a_kseg+1][a_row+64] = ra1.y;
            As[nb][a_kseg+2][a_row+64] = ra1.z; As[nb][a_kseg+3][a_row+64] = ra1.w;
            Bs[nb][b_kseg+0][b_row] = rb.x; Bs[nb][b_kseg+1][b_row] = rb.y;
            Bs[nb][b_kseg+2][b_row] = rb.z; Bs[nb][b_kseg+3][b_row] = rb.w;
            __syncthreads();
            buf = nb;
        }
    }

#pragma unroll
    for (int i = 0; i < 8; i++) {
        size_t row = (size_t)b * NN + bm + ty * 8 + i;
        int col = tx * 4;
#pragma unroll
        for (int j = 0; j < 4; j++)
            atomicAdd(&g_out64[row * DK + col + j], acc[i][j]);
    }
}

// ---------------- V transpose: g_VT[b][d][j] = g_V[b][j][d] -----------------
__global__ void transpose_v_kernel()
{
    __shared__ float tile[32][33];
    int b = blockIdx.z;
    int j0 = blockIdx.x * 32;
    int d0 = blockIdx.y * 32;
    int x = threadIdx.x, y = threadIdx.y;   // 32 x 8
    const float* Vb = g_V + (size_t)b * NN * DK;
    float* VTb = g_VT + (size_t)b * DK * NN;
#pragma unroll
    for (int yy = y; yy < 32; yy += 8)
        tile[yy][x] = Vb[(size_t)(j0 + yy) * DK + d0 + x];
    __syncthreads();
#pragma unroll
    for (int yy = y; yy < 32; yy += 8)
        VTb[(size_t)(d0 + yy) * NN + j0 + x] = tile[x][yy];
}

__global__ void zero_out64_kernel()
{
    int idx = blockIdx.x * 1024 + threadIdx.x;
    g_out64[idx] = 0.f;
}

// ---------------- features / Q / K / charge from h -----------------
__global__ void feat_qk_kernel(const float* __restrict__ w2, const float* __restrict__ b2,
                               const float* __restrict__ wq, const float* __restrict__ wk,
                               const float* __restrict__ wc, const float* __restrict__ bc)
{
    __shared__ float w2T[H1 * FF];
    __shared__ float wqT[FF * DK];
    __shared__ float wkT[FF * DK];
    __shared__ float wcs[FF];
    __shared__ float b2s[FF];
    __shared__ float hrow[8 * H1];
    __shared__ float feats[8 * FF];

    int tid = threadIdx.x;
    for (int idx = tid; idx < FF * H1; idx += 256) {
        int f = idx / H1, k = idx % H1;
        w2T[k * FF + f] = w2[idx];
    }
    for (int idx = tid; idx < DK * FF; idx += 256) {
        int d = idx / FF, f = idx % FF;
        wqT[f * DK + d] = wq[idx];
        wkT[f * DK + d] = wk[idx];
    }
    if (tid < FF) { wcs[tid] = wc[tid]; b2s[tid] = b2[tid]; }
    __syncthreads();

    int w = tid >> 5, lane = tid & 31;
    int g = blockIdx.x * 8 + w;
    const float* hr = g_h + (size_t)g * H1;
    hrow[w * H1 + lane      ] = hr[lane];
    hrow[w * H1 + lane + 32 ] = hr[lane + 32];
    hrow[w * H1 + lane + 64 ] = hr[lane + 64];
    hrow[w * H1 + lane + 96 ] = hr[lane + 96];
    __syncwarp();

    if (lane < FF) {
        float acc = b2s[lane];
#pragma unroll 4
        for (int k = 0; k < H1; k++)
            acc = fmaf(hrow[w * H1 + k], w2T[k * FF + lane], acc);
        feats[w * FF + lane] = 1.f / (1.f + expf(-acc));
    }
    __syncwarp();

    if (lane == 0) {
        float cc = bc[0];
        for (int f = 0; f < FF; f++) cc += feats[w * FF + f] * wcs[f];
        g_charge[g] = 1.f / (1.f + expf(-cc));
    }

#pragma unroll
    for (int dd = 0; dd < 2; dd++) {
        int d = lane + dd * 32;
        float q = 0.f, kk = 0.f;
#pragma unroll
        for (int f = 0; f < FF; f++) {
            float fv = feats[w * FF + f];
            q  = fmaf(fv, wqT[f * DK + d], q);
            kk = fmaf(fv, wkT[f * DK + d], kk);
        }
        g_Q[(size_t)g * DK + d] = q;
        g_K[(size_t)g * DK + d] = kk;
    }
}

// ---------------- softmax pass t: 8 rows/block, no-max, __expf, column sums ----------
#define PROWS 8
__global__ void softmax_pass_kernel(int nterms, const float* __restrict__ step_ptr)
{
    extern __shared__ float sm[];
    float* rowbuf = sm;                    // PROWS*NN
    float* chs    = sm + PROWS * NN;       // 4*NN (only j < r0+PROWS loaded)
    float* invs   = chs + 4 * NN;          // PROWS

    int b = blockIdx.y, r0 = blockIdx.x * PROWS;
    int tid = threadIdx.x, w = tid >> 5, lane = tid & 31;
    float step = *step_ptr;
    int jlim = r0 + PROWS;

    for (int s = 0; s < nterms; s++)
        for (int j = tid; j < jlim; j += 256)
            chs[s * NN + j] = g_chist[s * MM + b * NN + j];
    __syncthreads();

    int i = r0 + w;
    int len = i + 1;
    const float* crow = g_compat + ((size_t)b * NN + i) * NN;
    float* rb = rowbuf + w * NN;

    float a0 = 0.f, a1 = 0.f, a2 = 0.f, a3 = 0.f;
    if (nterms > 0) a0 = step * chs[i];
    if (nterms > 1) a1 = step * chs[NN + i];
    if (nterms > 2) a2 = step * chs[2 * NN + i];
    if (nterms > 3) a3 = step * chs[3 * NN + i];

    float s = 0.f;
    for (int j = lane; j < len; j += 32) {
        float m = 1.f;
        if (nterms > 0) m = fmaf(a0, chs[j], m);
        if (nterms > 1) m = fmaf(a1, chs[NN + j], m);
        if (nterms > 2) m = fmaf(a2, chs[2 * NN + j], m);
        if (nterms > 3) m = fmaf(a3, chs[3 * NN + j], m);
        float e = __expf(crow[j] * m);
        rb[j] = e;
        s += e;
    }
#pragma unroll
    for (int o = 16; o; o >>= 1) s += __shfl_xor_sync(0xffffffffu, s, o);
    if (lane == 0) invs[w] = 1.f / s;
    __syncthreads();

    // column reduction: recv[j] += sum over rows i=r0+w >= j (within this block)
    int jmax = jlim; if (jmax > NN) jmax = NN;
    for (int j = tid; j < jmax; j += 256) {
        float acc = 0.f;
        int wstart = (j > r0) ? (j - r0) : 0;
        for (int ww = wstart; ww < PROWS; ww++)
            acc += rowbuf[ww * NN + j] * invs[ww];
        atomicAdd(&g_recv[b * NN + j], acc);
    }
}

// ---------------- row sums of final exp (no materialization) -----------------
__global__ void rowsum_kernel(const float* __restrict__ step_ptr)
{
    __shared__ float chs[4 * NN];          // 32 KB
    int b = blockIdx.y, r0 = blockIdx.x * PROWS;
    int tid = threadIdx.x, w = tid >> 5, lane = tid & 31;
    float step = *step_ptr;
    int jlim = r0 + PROWS;

    for (int s = 0; s < 4; s++)
        for (int j = tid; j < jlim; j += 256)
            chs[s * NN + j] = g_chist[s * MM + b * NN + j];
    __syncthreads();

    int i = r0 + w;
    int len = i + 1;
    const float* crow = g_compat + ((size_t)b * NN + i) * NN;

    float a0 = step * chs[i];
    float a1 = step * chs[NN + i];
    float a2 = step * chs[2 * NN + i];
    float a3 = step * chs[3 * NN + i];

    float s = 0.f;
    for (int j = lane; j < len; j += 32) {
        float m = 1.f;
        m = fmaf(a0, chs[j], m);
        m = fmaf(a1, chs[NN + j], m);
        m = fmaf(a2, chs[2 * NN + j], m);
        m = fmaf(a3, chs[3 * NN + j], m);
        s += __expf(crow[j] * m);
    }
#pragma unroll
    for (int o = 16; o; o >>= 1) s += __shfl_xor_sync(0xffffffffu, s, o);
    if (lane == 0) g_rowinv[b * NN + i] = 1.f / s;
}

// ---------------- charge update + recv re-zero -----------------
__global__ void charge_update_kernel(int t, const float* __restrict__ decay_ptr)
{
    int idx = blockIdx.x * 256 + threadIdx.x;
    float r = g_recv[idx];
    g_recv[idx] = 0.f;
    float d = *decay_ptr;
    float sg = 1.f / (1.f + expf(-(r - 1.f)));
    float c = g_charge[idx] * (1.f - d * sg);
    g_charge[idx] = c;
    g_chist[t * MM + idx] = c;
}

// =====================================================================================
extern "C" void kernel_launch(void* const* d_in, const int* in_sizes, int n_in,
                              void* d_out, int out_size)
{
    const float* hs      = (const float*)d_in[0];
    const float* w1      = (const float*)d_in[2];
    const float* b1      = (const float*)d_in[3];
    const float* w2      = (const float*)d_in[4];
    const float* b2      = (const float*)d_in[5];
    const float* wq      = (const float*)d_in[6];
    const float* wk      = (const float*)d_in[7];
    const float* wc      = (const float*)d_in[8];
    const float* bc      = (const float*)d_in[9];
    const float* step_p  = (const float*)d_in[10];
    const float* decay_p = (const float*)d_in[11];
    const float* wv      = (const float*)d_in[12];
    const float* wo      = (const float*)d_in[13];
    const float* alpha_p = (const float*)d_in[14];
    float* out = (float*)d_out;

    float *ph, *pV, *pQ, *pK, *po64, *pC;
    cudaGetSymbolAddress((void**)&ph,   g_h);
    cudaGetSymbolAddress((void**)&pV,   g_V);
    cudaGetSymbolAddress((void**)&pQ,   g_Q);
    cudaGetSymbolAddress((void**)&pK,   g_K);
    cudaGetSymbolAddress((void**)&po64, g_out64);
    cudaGetSymbolAddress((void**)&pC,   g_compat);

    const int smem_pass = (PROWS * NN + 4 * NN + PROWS) * 4;   // ~98.3 KB
    cudaFuncSetAttribute(softmax_pass_kernel,
                         cudaFuncAttributeMaxDynamicSharedMemorySize, smem_pass);

    // 1) h = gelu(hs @ w1^T + b1)
    gemm_tile_kernel<EPI_GELU_BIAS,false><<<dim3(H1/TBN, MM/TBM, 1), 256>>>(
        hs, w1, b1, ph, H1, DD, 0, 0, 0, nullptr);

    // 2) features -> Q, K, charge0
    feat_qk_kernel<<<MM / 8, 256>>>(w2, b2, wq, wk, wc, bc);

    // 3) V = hs @ wv^T
    gemm_tile_kernel<EPI_NONE,false><<<dim3(DK/TBN, MM/TBM, 1), 256>>>(
        hs, wv, nullptr, pV, DK, DD, 0, 0, 0, nullptr);

    // 4) VT[b][d][j] = V[b][j][d]
    transpose_v_kernel<<<dim3(NN/32, DK/32, BB), dim3(32, 8)>>>();

    // 5) compat = Q @ K^T / 8 (triangular tile set)
    gemm_tile_kernel<EPI_SCALE,true><<<dim3(NN/TBN, NN/TBM, BB), 256>>>(
        pQ, pK, nullptr, pC, NN, DK,
        (size_t)NN*DK, (size_t)NN*DK, (size_t)NN*NN, nullptr);

    // 6) 4 charge iterations                      (launch #6 = pass t=0 -> profiled)
    for (int t = 0; t < NSTEPS; t++) {
        softmax_pass_kernel<<<dim3(NN/PROWS, BB), 256, smem_pass>>>(t, step_p);
        charge_update_kernel<<<MM/256, 256>>>(t, decay_p);
    }

    // 7) row sums of final softmax (1/sum of exp)
    rowsum_kernel<<<dim3(NN/PROWS, BB), 256>>>(step_p);

    // 8) out64 = softmax(logits) @ V, exp fused into A loader, split-K=4
    zero_out64_kernel<<<(MM*DK)/1024, 1024>>>();
    attn_v_fused_kernel<<<dim3(4, NN/TBM, BB), 256>>>(step_p);

    // 9) out = alpha * (out64 @ wo^T)
    gemm_tile_kernel<EPI_ALPHA,false><<<dim3(DD/TBN, MM/TBM, 1), 256>>>(
        po64, wo, nullptr, out, DD, DK, 0, 0, 0, alpha_p);
}